// round 10
// baseline (speedup 1.0000x reference)
#include <cuda_runtime.h>
#include <cstdint>
#include <cfloat>

// Sparsemax (d = 4096) — per-warp-seeded Michelot with candidate compaction.
//
//   thr_w = warp_max - 1  (<= M-1 <= tau*): each warp's survivors form a
//   superset of the support; the union buffer B also does. Warp 0 runs
//   Michelot on B starting at thr = M-1; any fixed point solves
//   sum((x - tau)+) = 1 exactly over the row, so tau = tau*.
//
//   Critical path: loads -> warp max (REDUX) -> compact (atomicAdd) ->
//   [one real barrier] -> warp-0 tail -> [barrier] -> store.
//   No block max round-trip, no block (sum,count) reduce.

#define ROW_D     4096
#define THREADS   256
#define NW        (THREADS / 32)
#define V4_PER_T  4

__device__ __forceinline__ unsigned f2key(float f) {
    const unsigned b = __float_as_uint(f);
    return b ^ ((unsigned)((int)b >> 31) | 0x80000000u);
}
__device__ __forceinline__ float key2f(unsigned k) {
    return __uint_as_float(k ^ ((unsigned)((int)(~k) >> 31) | 0x80000000u));
}

__global__ __launch_bounds__(THREADS, 6)
void sparsemax_kernel(const float* __restrict__ x, float* __restrict__ out)
{
    __shared__ float s_max[NW];
    __shared__ int   s_n;
    __shared__ float s_tau;
    __shared__ float s_buf[ROW_D];    // worst case: all elements survive

    const size_t row_base = (size_t)blockIdx.x * ROW_D;
    const float4* __restrict__ xr  = reinterpret_cast<const float4*>(x + row_base);
    float4*       __restrict__ orr = reinterpret_cast<float4*>(out + row_base);

    const int tid = threadIdx.x;
    const int wid = tid >> 5;
    const int lid = tid & 31;

    // ---- issue row loads first (DRAM latency runs under the init barrier) ----
    float4 v4[V4_PER_T];
#pragma unroll
    for (int i = 0; i < V4_PER_T; ++i)
        v4[i] = __ldcs(&xr[tid + i * THREADS]);

    if (tid == 0) s_n = 0;
    __syncthreads();                  // free barrier: no warp skew yet

    // ---- per-warp max via REDUX (no block barrier) ----
    float m = -FLT_MAX;
#pragma unroll
    for (int i = 0; i < V4_PER_T; ++i) {
        const float4 q = v4[i];
        m = fmaxf(m, fmaxf(fmaxf(q.x, q.y), fmaxf(q.z, q.w)));
    }
    m = key2f(__reduce_max_sync(0xFFFFFFFFu, f2key(m)));
    const float thr = m - 1.0f;       // <= M-1 <= tau*  => superset per warp

    // ---- compact this warp's survivors into the shared buffer ----
    int myc = 0;
#pragma unroll
    for (int i = 0; i < V4_PER_T; ++i) {
        const float4 q = v4[i];
        myc += (q.x > thr) + (q.y > thr) + (q.z > thr) + (q.w > thr);
    }
    if (myc > 0) {
        int pos = atomicAdd(&s_n, myc);
#pragma unroll
        for (int i = 0; i < V4_PER_T; ++i) {
            const float4 q = v4[i];
            if (q.x > thr) s_buf[pos++] = q.x;
            if (q.y > thr) s_buf[pos++] = q.y;
            if (q.z > thr) s_buf[pos++] = q.z;
            if (q.w > thr) s_buf[pos++] = q.w;
        }
    }
    if (lid == 0) s_max[wid] = m;
    __syncthreads();                  // barrier A (the only mid-path barrier)

    // ---- warp 0: Michelot over the compacted buffer ----
    if (wid == 0) {
        float M = s_max[0];
#pragma unroll
        for (int w = 1; w < NW; ++w) M = fmaxf(M, s_max[w]);
        const int n = s_n;

        float tau  = M - 1.0f;        // iteration 1 thresholds at M-1
        int   prev = -1;

        for (int iter = 0; iter < 64; ++iter) {
            float ls = 0.0f;
            int   lc = 0;
            for (int j = lid; j < n; j += 32) {
                const float vv = s_buf[j];
                if (vv > tau) { ls += vv; ++lc; }
            }
#pragma unroll
            for (int o = 16; o > 0; o >>= 1)
                ls += __shfl_xor_sync(0xFFFFFFFFu, ls, o);
            lc = __reduce_add_sync(0xFFFFFFFFu, lc);

            tau = (ls - 1.0f) / (float)lc;   // lc >= 1: row max always > tau
            if (lc == prev) break;           // set unchanged -> fixed point -> tau*
            prev = lc;
        }
        if (lid == 0) s_tau = tau;
    }
    __syncthreads();                  // barrier B
    const float tau = s_tau;

    // ---- epilogue: out = max(x - tau, 0), streaming stores ----
#pragma unroll
    for (int i = 0; i < V4_PER_T; ++i) {
        const float4 q = v4[i];
        float4 o;
        o.x = fmaxf(q.x - tau, 0.0f);
        o.y = fmaxf(q.y - tau, 0.0f);
        o.z = fmaxf(q.z - tau, 0.0f);
        o.w = fmaxf(q.w - tau, 0.0f);
        __stcs(&orr[tid + i * THREADS], o);
    }
}

extern "C" void kernel_launch(void* const* d_in, const int* in_sizes, int n_in,
                              void* d_out, int out_size)
{
    const float* x   = (const float*)d_in[0];
    float*       out = (float*)d_out;
    const int n_rows = in_sizes[0] / ROW_D;   // 16384
    sparsemax_kernel<<<n_rows, THREADS>>>(x, out);
}

// round 11
// speedup vs baseline: 1.1443x; 1.1443x over previous
#include <cuda_runtime.h>
#include <cstdint>
#include <cfloat>

// Sparsemax (d = 4096), max-seeded Michelot, row staged in SMEM.
//
//   Pass 1: load row (streaming), per-warp max, stash row -> s_row. [bar 1]
//   Block max M; thr0 = M-1 (tau* >= M-1 => survivors superset of support).
//   Pass 2: re-read row from SMEM, compact survivors -> s_buf.      [bar 2]
//   Warp 0: Michelot on the ~60 candidates (fallback: scan s_row if
//   the 512-entry buffer overflows — degenerate rows only).         [bar 3]
//   Epilogue: out = max(row - tau, 0) from SMEM.
//
// Row in SMEM (not registers) => ~32 regs/thread => 8 CTAs/SM (full
// occupancy) for smoother DRAM pipelining across CTA phases.

#define ROW_D     4096
#define THREADS   256
#define NW        (THREADS / 32)
#define V4_PER_T  4
#define CAND_MAX  512

__device__ __forceinline__ unsigned f2key(float f) {
    const unsigned b = __float_as_uint(f);
    return b ^ ((unsigned)((int)b >> 31) | 0x80000000u);
}
__device__ __forceinline__ float key2f(unsigned k) {
    return __uint_as_float(k ^ ((unsigned)((int)(~k) >> 31) | 0x80000000u));
}

__global__ __launch_bounds__(THREADS, 8)
void sparsemax_kernel(const float* __restrict__ x, float* __restrict__ out)
{
    __shared__ float  s_max[NW];
    __shared__ int    s_n;
    __shared__ float  s_tau;
    __shared__ float  s_buf[CAND_MAX];
    __shared__ float4 s_row[ROW_D / 4];   // 16 KB: the whole row

    const size_t row_base = (size_t)blockIdx.x * ROW_D;
    const float4* __restrict__ xr  = reinterpret_cast<const float4*>(x + row_base);
    float4*       __restrict__ orr = reinterpret_cast<float4*>(out + row_base);

    const int tid = threadIdx.x;
    const int wid = tid >> 5;
    const int lid = tid & 31;

    // ---- pass 1: load row, track max, stash to SMEM ----
    float m = -FLT_MAX;
#pragma unroll
    for (int i = 0; i < V4_PER_T; ++i) {
        const float4 q = __ldcs(&xr[tid + i * THREADS]);
        m = fmaxf(m, fmaxf(fmaxf(q.x, q.y), fmaxf(q.z, q.w)));
        s_row[tid + i * THREADS] = q;
    }
    m = key2f(__reduce_max_sync(0xFFFFFFFFu, f2key(m)));
    if (lid == 0) s_max[wid] = m;
    if (tid == 0) s_n = 0;
    __syncthreads();                                   // barrier 1

    float M = s_max[0];
#pragma unroll
    for (int w = 1; w < NW; ++w) M = fmaxf(M, s_max[w]);
    const float thr0 = M - 1.0f;                       // <= tau*

    // ---- pass 2: compact survivors (values re-read from SMEM) ----
    int myc = 0;
#pragma unroll
    for (int i = 0; i < V4_PER_T; ++i) {
        const float4 q = s_row[tid + i * THREADS];
        myc += (q.x > thr0) + (q.y > thr0) + (q.z > thr0) + (q.w > thr0);
    }
    if (myc > 0) {
        int pos = atomicAdd(&s_n, myc);
#pragma unroll
        for (int i = 0; i < V4_PER_T; ++i) {
            const float4 q = s_row[tid + i * THREADS];
            if (q.x > thr0) { if (pos < CAND_MAX) s_buf[pos] = q.x; ++pos; }
            if (q.y > thr0) { if (pos < CAND_MAX) s_buf[pos] = q.y; ++pos; }
            if (q.z > thr0) { if (pos < CAND_MAX) s_buf[pos] = q.z; ++pos; }
            if (q.w > thr0) { if (pos < CAND_MAX) s_buf[pos] = q.w; ++pos; }
        }
    }
    __syncthreads();                                   // barrier 2

    // ---- warp 0: Michelot over candidates ----
    if (wid == 0) {
        const int  n        = s_n;
        const bool overflow = (n > CAND_MAX);          // degenerate rows only
        const float* __restrict__ src = overflow
            ? reinterpret_cast<const float*>(s_row) : s_buf;
        const int  nn = overflow ? ROW_D : n;

        float tau  = thr0;     // first pass reproduces iter-1 over survivors
        int   prev = -1;

        for (int iter = 0; iter < 64; ++iter) {
            float ls = 0.0f;
            int   lc = 0;
            for (int j = lid; j < nn; j += 32) {
                const float vv = src[j];
                if (vv > tau) { ls += vv; ++lc; }
            }
#pragma unroll
            for (int o = 16; o > 0; o >>= 1)
                ls += __shfl_xor_sync(0xFFFFFFFFu, ls, o);
            lc = __reduce_add_sync(0xFFFFFFFFu, lc);

            tau = (ls - 1.0f) / (float)lc;   // lc >= 1: row max always > tau
            if (lc == prev) break;           // fixed point -> tau = tau*
            prev = lc;
        }
        if (lid == 0) s_tau = tau;
    }
    __syncthreads();                                   // barrier 3
    const float tau = s_tau;

    // ---- epilogue: out = max(row - tau, 0) from SMEM ----
#pragma unroll
    for (int i = 0; i < V4_PER_T; ++i) {
        const float4 q = s_row[tid + i * THREADS];
        float4 o;
        o.x = fmaxf(q.x - tau, 0.0f);
        o.y = fmaxf(q.y - tau, 0.0f);
        o.z = fmaxf(q.z - tau, 0.0f);
        o.w = fmaxf(q.w - tau, 0.0f);
        __stcs(&orr[tid + i * THREADS], o);
    }
}

extern "C" void kernel_launch(void* const* d_in, const int* in_sizes, int n_in,
                              void* d_out, int out_size)
{
    const float* x   = (const float*)d_in[0];
    float*       out = (float*)d_out;
    const int n_rows = in_sizes[0] / ROW_D;   // 16384
    sparsemax_kernel<<<n_rows, THREADS>>>(x, out);
}